// round 5
// baseline (speedup 1.0000x reference)
#include <cuda_runtime.h>

// Problem constants (fixed by the reference: x=(128,128,16,16) f32, logits=(128,100))
#define B_  128
#define D_  32768          // C*H*W
#define D4_ (D_/4)         // 8192 float4 per prototype row
#define K_  100
#define TILE_ 10           // 10x10 class tile per block

// ---------------------------------------------------------------------------
// ONE fully fused kernel: argmax + CSR (redundant per block, smem-only) +
// prototypes + inter-class matrix.
//
// grid = (D4/256, 100 tiles of 10x10 classes), block = 256.
//
// Phase A (per-block, ~1-2K cycles): argmax of softmax(logits) per batch row
//   == argmax(logits) (softmax monotone). 2 threads/row, strided scan with
//   strict > (ascending => lowest index on ties, matching jnp.argmax), pair
//   combined by shuffle. CSR built in smem: counts via smem atomics
//   (order-independent), serial prefix on thread 0, stable rank scan.
//   Every block computes the identical CSR from the same logits ->
//   deterministic. logits (51 KB) are L2-resident after the first wave, so
//   the redundant reads cost ~163 MB of L2 traffic (~0.8 TB/s) against an
//   ~11 TB/s L2 cap — free under the DRAM-bound main loop.
//
// Phase B: recompute the tile's 20 prototype rows from x in CSR order
//   (bitwise-identical across blocks), pj[10] in registers; pi streamed.
//   x (16 MB) is L2-resident. Diagonal tiles publish the prototype output.
//   All output stores __stcs (evict-first): the 1.31 GB write stream is
//   never re-read; keep x/logits resident in L2.
//
// Bound: DRAM writes (1.325 GB mandatory output), measured ~6.4 TB/s.
// ---------------------------------------------------------------------------
__global__ __launch_bounds__(256) void fused_kernel(
        const float*  __restrict__ logits,
        const float4* __restrict__ x4,
        float4* __restrict__ proto4,
        float4* __restrict__ out4) {
    __shared__ int   s_cls[B_];
    __shared__ int   s_cnt[K_];
    __shared__ int   s_off[K_ + 1];
    __shared__ int   s_items[B_];
    __shared__ float s_inv[K_];

    const int t = threadIdx.x;        // 0..255

    // ---- Phase A: argmax per row (2 threads per row) ----
    if (t < K_) s_cnt[t] = 0;

    {
        const int b   = t >> 1;       // row 0..127
        const int sub = t & 1;        // 0..1
        const float* row = logits + (size_t)b * K_;
        float v   = row[sub];
        int   idx = sub;
        #pragma unroll
        for (int k = sub + 2; k < K_; k += 2) {
            float u = row[k];
            if (u > v) { v = u; idx = k; }    // ascending + strict > => lowest index
        }
        float ov = __shfl_xor_sync(0xffffffffu, v,   1);
        int   oi = __shfl_xor_sync(0xffffffffu, idx, 1);
        if (ov > v || (ov == v && oi < idx)) { v = ov; idx = oi; }
        __syncthreads();              // counts zeroed before atomics
        if (sub == 0) {
            s_cls[b] = idx;
            atomicAdd(&s_cnt[idx], 1);
        }
    }
    __syncthreads();

    // serial prefix over 100 smem ints
    if (t == 0) {
        int off = 0;
        #pragma unroll 4
        for (int k = 0; k < K_; k++) { s_off[k] = off; off += s_cnt[k]; }
        s_off[K_] = off;
    }
    if (t < K_) {
        int c = s_cnt[t];
        s_inv[t] = (c > 0) ? (1.0f / (float)c) : 0.0f;
    }
    __syncthreads();

    // stable rank scan -> CSR items (threads 0..127)
    if (t < B_) {
        int myc = s_cls[t];
        int rank = 0;
        #pragma unroll 8
        for (int bb = 0; bb < B_; bb++)
            rank += (bb < t && s_cls[bb] == myc) ? 1 : 0;
        s_items[s_off[myc] + rank] = t;
    }
    __syncthreads();

    // ---- Phase B: prototypes + inter-class tile ----
    const int d4   = blockIdx.x * 256 + t;          // 0..D4-1
    const int tile = blockIdx.y;                    // 0..99
    const int i0 = (tile / TILE_) * TILE_;
    const int j0 = (tile % TILE_) * TILE_;
    const bool diag = (i0 == j0);

    float4 pj[TILE_];
    #pragma unroll
    for (int jj = 0; jj < TILE_; jj++) {
        const int k = j0 + jj;
        float4 acc = make_float4(0.f, 0.f, 0.f, 0.f);
        const int s = s_off[k], e = s_off[k + 1];
        for (int u = s; u < e; u++) {
            float4 v = x4[(size_t)s_items[u] * D4_ + d4];
            acc.x += v.x; acc.y += v.y; acc.z += v.z; acc.w += v.w;
        }
        const float inv = s_inv[k];   // count==0 -> acc==0, inv==0 -> 0 (matches where())
        acc.x *= inv; acc.y *= inv; acc.z *= inv; acc.w *= inv;
        pj[jj] = acc;
    }

    if (diag) {
        #pragma unroll
        for (int jj = 0; jj < TILE_; jj++)
            __stcs(&proto4[(size_t)(j0 + jj) * D4_ + d4], pj[jj]);
    }

    #pragma unroll
    for (int ii = 0; ii < TILE_; ii++) {
        const int k = i0 + ii;
        float4 pi;
        if (diag) {
            pi = pj[ii];
        } else {
            float4 acc = make_float4(0.f, 0.f, 0.f, 0.f);
            const int s = s_off[k], e = s_off[k + 1];
            for (int u = s; u < e; u++) {
                float4 v = x4[(size_t)s_items[u] * D4_ + d4];
                acc.x += v.x; acc.y += v.y; acc.z += v.z; acc.w += v.w;
            }
            const float inv = s_inv[k];
            acc.x *= inv; acc.y *= inv; acc.z *= inv; acc.w *= inv;
            pi = acc;
        }
        #pragma unroll
        for (int jj = 0; jj < TILE_; jj++) {
            float4 r;
            r.x = pj[jj].x - pi.x;
            r.y = pj[jj].y - pi.y;
            r.z = pj[jj].z - pi.z;
            r.w = pj[jj].w - pi.w;
            __stcs(&out4[(size_t)((i0 + ii) * K_ + (j0 + jj)) * D4_ + d4], r);
        }
    }
}

// ---------------------------------------------------------------------------
// Launcher. Output layout: [prototypes (100*32768 f32) | inter (100*100*32768 f32)]
// ---------------------------------------------------------------------------
extern "C" void kernel_launch(void* const* d_in, const int* in_sizes, int n_in,
                              void* d_out, int out_size) {
    const float* x      = (const float*)d_in[0];   // (128,128,16,16) f32
    const float* logits = (const float*)d_in[1];   // (128,100) f32
    float* out = (float*)d_out;

    const float4* x4     = (const float4*)x;
    float4*       proto4 = (float4*)out;                       // first 819200 float4
    float4*       inter4 = (float4*)out + (size_t)K_ * D4_;    // rest

    dim3 gi(D4_ / 256, K_);        // 32 x 100 tiles (10x10 class tiles)
    fused_kernel<<<gi, 256>>>(logits, x4, proto4, inter4);
}

// round 6
// speedup vs baseline: 1.1430x; 1.1430x over previous
#include <cuda_runtime.h>

// Problem constants (fixed by the reference: x=(128,128,16,16) f32, logits=(128,100))
#define B_  128
#define D_  32768          // C*H*W
#define D4_ (D_/4)         // 8192 float4 per prototype row
#define K_  100
#define TILE_ 10           // 10x10 class tile in the fused broadcast kernel

// Scratch (allocation-free rule: __device__ globals)
__device__ int   g_items[B_];    // CSR items: batch indices grouped by class, ascending
__device__ int   g_off[K_ + 1];  // CSR offsets
__device__ float g_inv[K_];      // 1/count (0 if count==0)

// ---------------------------------------------------------------------------
// Kernel 1: argmax per batch row + deterministic CSR build (single block).
// 1024 threads, 8 per row -> high MLP on the 51 KB logits read.
// softmax is monotone -> argmax(probs) == argmax(logits); strict > with
// ascending scan + (value,index) shuffle reduce matches jnp.argmax ties.
// CSR: counts via smem atomics (order-independent), serial smem prefix,
// stable rank scan -> bitwise-deterministic.
// Ends with a PDL trigger so the dependent kernel can proceed the moment the
// g_* publishes are visible.
// ---------------------------------------------------------------------------
__global__ __launch_bounds__(1024) void argmax_csr_kernel(
        const float* __restrict__ logits) {
    __shared__ int s_cls[B_];
    __shared__ int s_cnt[K_];
    __shared__ int s_off[K_ + 1];

    int tid = threadIdx.x;        // 0..1023
    int b   = tid >> 3;           // row 0..127
    int sub = tid & 7;            // 0..7 within row

    if (tid < K_) s_cnt[tid] = 0;

    const float* row = logits + (size_t)b * K_;
    float v   = row[sub];
    int   idx = sub;
    #pragma unroll
    for (int k = sub + 8; k < K_; k += 8) {
        float t = row[k];
        if (t > v) { v = t; idx = k; }   // ascending + strict > => lowest index kept
    }
    #pragma unroll
    for (int off = 4; off > 0; off >>= 1) {
        float ov = __shfl_down_sync(0xffffffffu, v,   off, 8);
        int   oi = __shfl_down_sync(0xffffffffu, idx, off, 8);
        if (ov > v || (ov == v && oi < idx)) { v = ov; idx = oi; }
    }
    __syncthreads();              // counts zeroed before atomics
    if (sub == 0) {
        s_cls[b] = idx;
        atomicAdd(&s_cnt[idx], 1);
    }
    __syncthreads();

    if (tid == 0) {
        int off = 0;
        #pragma unroll 4
        for (int k = 0; k < K_; k++) { s_off[k] = off; off += s_cnt[k]; }
        s_off[K_] = off;
    }
    __syncthreads();

    if (tid < B_) {
        int myc = s_cls[tid];
        int rank = 0;
        #pragma unroll 8
        for (int bb = 0; bb < B_; bb++)
            rank += (bb < tid && s_cls[bb] == myc) ? 1 : 0;
        g_items[s_off[myc] + rank] = tid;
    }

    if (tid < K_) {
        g_off[tid] = s_off[tid];
        int c = s_cnt[tid];
        g_inv[tid] = (c > 0) ? (1.0f / (float)c) : 0.0f;
    }
    if (tid == 0) g_off[K_] = s_off[K_];

    // All g_* writes by this thread are done -> allow the dependent grid.
    cudaTriggerProgrammaticLaunchCompletion();
}

// ---------------------------------------------------------------------------
// Kernel 2 (fused): prototypes + inter-class matrix. Identical math to R4.
// grid = (D4/256, 100 tiles of 10x10 classes), block = 256, 64 regs.
// Recomputes its 20 prototype rows from x in CSR order (bitwise-identical
// across blocks); pj[10] in registers, pi streamed; x (16 MB) L2-resident.
// Diagonal tiles publish the prototype output. __stcs on the 1.31 GB write
// stream (never re-read). DRAM-write-bound at ~80% of spec.
// PDL: launched concurrently with kernel 1; waits on its completion before
// touching g_*.
// ---------------------------------------------------------------------------
__global__ __launch_bounds__(256) void inter_fused_kernel(
        const float4* __restrict__ x4,
        float4* __restrict__ proto4,
        float4* __restrict__ out4) {
    __shared__ int   s_off[K_ + 1];
    __shared__ int   s_items[B_];
    __shared__ float s_inv[K_];

    // Wait for argmax_csr_kernel's g_* publishes (PDL dependency).
    cudaGridDependencySynchronize();

    int t = threadIdx.x;
    if (t < K_ + 1) s_off[t]   = g_off[t];
    if (t < B_)     s_items[t] = g_items[t];
    if (t < K_)     s_inv[t]   = g_inv[t];
    __syncthreads();

    int d4   = blockIdx.x * 256 + t;               // 0..D4-1
    int tile = blockIdx.y;                         // 0..99
    int i0 = (tile / TILE_) * TILE_;
    int j0 = (tile % TILE_) * TILE_;
    bool diag = (i0 == j0);

    float4 pj[TILE_];
    #pragma unroll
    for (int jj = 0; jj < TILE_; jj++) {
        int k = j0 + jj;
        float4 acc = make_float4(0.f, 0.f, 0.f, 0.f);
        int s = s_off[k], e = s_off[k + 1];
        for (int u = s; u < e; u++) {
            float4 v = x4[(size_t)s_items[u] * D4_ + d4];
            acc.x += v.x; acc.y += v.y; acc.z += v.z; acc.w += v.w;
        }
        float inv = s_inv[k];    // count==0 -> acc==0, inv==0 -> 0 (matches where())
        acc.x *= inv; acc.y *= inv; acc.z *= inv; acc.w *= inv;
        pj[jj] = acc;
    }

    if (diag) {
        #pragma unroll
        for (int jj = 0; jj < TILE_; jj++)
            __stcs(&proto4[(size_t)(j0 + jj) * D4_ + d4], pj[jj]);
    }

    #pragma unroll
    for (int ii = 0; ii < TILE_; ii++) {
        int k = i0 + ii;
        float4 pi;
        if (diag) {
            pi = pj[ii];
        } else {
            float4 acc = make_float4(0.f, 0.f, 0.f, 0.f);
            int s = s_off[k], e = s_off[k + 1];
            for (int u = s; u < e; u++) {
                float4 v = x4[(size_t)s_items[u] * D4_ + d4];
                acc.x += v.x; acc.y += v.y; acc.z += v.z; acc.w += v.w;
            }
            float inv = s_inv[k];
            acc.x *= inv; acc.y *= inv; acc.z *= inv; acc.w *= inv;
            pi = acc;
        }
        #pragma unroll
        for (int jj = 0; jj < TILE_; jj++) {
            float4 r;
            r.x = pj[jj].x - pi.x;
            r.y = pj[jj].y - pi.y;
            r.z = pj[jj].z - pi.z;
            r.w = pj[jj].w - pi.w;
            __stcs(&out4[(size_t)((i0 + ii) * K_ + (j0 + jj)) * D4_ + d4], r);
        }
    }
}

// ---------------------------------------------------------------------------
// Launcher. Output layout: [prototypes (100*32768 f32) | inter (100*100*32768 f32)]
// Kernel 2 is launched with PDL (programmatic stream serialization) so its
// launch + early phases overlap kernel 1's execution.
// ---------------------------------------------------------------------------
extern "C" void kernel_launch(void* const* d_in, const int* in_sizes, int n_in,
                              void* d_out, int out_size) {
    const float* x      = (const float*)d_in[0];   // (128,128,16,16) f32
    const float* logits = (const float*)d_in[1];   // (128,100) f32
    float* out = (float*)d_out;

    const float4* x4     = (const float4*)x;
    float4*       proto4 = (float4*)out;                       // first 819200 float4
    float4*       inter4 = (float4*)out + (size_t)K_ * D4_;    // rest

    argmax_csr_kernel<<<1, 1024>>>(logits);

    cudaLaunchConfig_t cfg = {};
    cfg.gridDim  = dim3(D4_ / 256, K_);   // 32 x 100 tiles
    cfg.blockDim = dim3(256);
    cfg.dynamicSmemBytes = 0;
    cfg.stream = 0;                        // same (default) stream as kernel 1
    cudaLaunchAttribute attrs[1];
    attrs[0].id = cudaLaunchAttributeProgrammaticStreamSerialization;
    attrs[0].val.programmaticStreamSerializationAllowed = 1;
    cfg.attrs = attrs;
    cfg.numAttrs = 1;
    cudaLaunchKernelEx(&cfg, inter_fused_kernel, x4, proto4, inter4);
}